// round 17
// baseline (speedup 1.0000x reference)
#include <cuda_runtime.h>
#include <cuda_bf16.h>
#include <cstdint>

#define N_NODES 1024
#define F_IN    32
#define HID     64
#define OUTF    32

typedef unsigned long long u64;

// Scratch
__device__ float    g_A   [N_NODES * HID];
__device__ float    g_Bq  [16 * N_NODES * 4];   // quad-packed: [hq][node][4]
__device__ uint16_t g_W2h [OUTF * HID];         // bf16(W2[o][h])
__device__ uint16_t g_W2l [OUTF * HID];         // bf16 residual
__device__ float    g_bias[96];                 // b1*0.5 (64) ++ b2 (32)

__constant__ float c_bias[96];

// ---------------------------------------------------------------------------
// Prep: 128 blocks x 256 threads, 8 nodes/block. Block 0 also writes W2 hi/lo
// bf16 tiles and the bias vector.
// ---------------------------------------------------------------------------
__global__ __launch_bounds__(256) void prep_kernel(const float* __restrict__ Emb,
                                                   const float* __restrict__ W1,
                                                   const float* __restrict__ W2,
                                                   const float* __restrict__ b1,
                                                   const float* __restrict__ b2) {
    __shared__ float sW1[HID * 65];
    __shared__ float sE[8 * F_IN];
    const int tid = threadIdx.x;
    const int i0  = blockIdx.x * 8;

    if (blockIdx.x == 0) {
        for (int idx = tid; idx < OUTF * HID; idx += 256) {
            float wv = W2[idx];
            __nv_bfloat16 h = __float2bfloat16(wv);
            __nv_bfloat16 l = __float2bfloat16(wv - __bfloat162float(h));
            g_W2h[idx] = __bfloat16_as_ushort(h);
            g_W2l[idx] = __bfloat16_as_ushort(l);
        }
        if (tid < HID) g_bias[tid] = 0.5f * b1[tid];
        else if (tid < HID + OUTF) g_bias[tid] = b2[tid - HID];
    }

    {
        const float4* w4 = (const float4*)W1;
        for (int v = tid; v < HID * 2 * F_IN / 4; v += 256) {
            float4 w = __ldg(w4 + v);
            int r = v >> 4, c = (v & 15) * 4;
            float* dst = &sW1[r * 65 + c];
            dst[0] = w.x; dst[1] = w.y; dst[2] = w.z; dst[3] = w.w;
        }
    }
    if (tid < 64) {
        float4 e = __ldg((const float4*)(Emb + i0 * F_IN) + tid);
        float* dst = &sE[tid * 4];
        dst[0] = e.x; dst[1] = e.y; dst[2] = e.z; dst[3] = e.w;
    }
    __syncthreads();

    const int h = tid & 63;
    const int g = tid >> 6;
#pragma unroll
    for (int k = 0; k < 2; k++) {
        const int n = g * 2 + k;
        const float* e = &sE[n * F_IN];
        float a = 0.f, b = 0.f;
#pragma unroll
        for (int f = 0; f < F_IN; f++) {
            float ev = e[f];
            a = fmaf(ev, sW1[h * 65 + f], a);
            b = fmaf(ev, sW1[h * 65 + F_IN + f], b);
        }
        const int i = i0 + n;
        g_A[i * HID + h] = a;
        g_Bq[(h >> 2) * (N_NODES * 4) + i * 4 + (h & 3)] = b;
    }
}

// ---------------------------------------------------------------------------
__device__ __forceinline__ u64 pack2(float lo, float hi) {
    u64 r; asm("mov.b64 %0, {%1,%2};" : "=l"(r) : "f"(lo), "f"(hi)); return r;
}
__device__ __forceinline__ void unpack2(u64 v, float& lo, float& hi) {
    asm("mov.b64 {%0,%1}, %2;" : "=f"(lo), "=f"(hi) : "l"(v));
}
__device__ __forceinline__ u64 fma2r(u64 a, u64 b, u64 c) {
    u64 d; asm("fma.rn.f32x2 %0, %1, %2, %3;" : "=l"(d) : "l"(a), "l"(b), "l"(c)); return d;
}
__device__ __forceinline__ u64 add2r(u64 a, u64 b) {
    u64 d; asm("add.rn.f32x2 %0, %1, %2;" : "=l"(d) : "l"(a), "l"(b)); return d;
}
__device__ __forceinline__ float tanhf_a(float x) {
    float t; asm("tanh.approx.f32 %0, %1;" : "=f"(t) : "f"(x)); return t;
}
__device__ __forceinline__ float swish_from_half(float hx) {
    return fmaf(hx, tanhf_a(hx), hx);
}
// pack two floats to bf16x2: a -> hi 16 bits, b -> lo 16 bits
__device__ __forceinline__ uint32_t cvt_bf16x2(float a, float b) {
    uint32_t r;
    asm("cvt.rn.bf16x2.f32 %0, %1, %2;" : "=r"(r) : "f"(a), "f"(b));
    return r;
}
__device__ __forceinline__ uint32_t smem_u32(const void* p) {
    uint32_t a;
    asm("{ .reg .u64 t; cvta.to.shared.u64 t, %1; cvt.u32.u64 %0, t; }"
        : "=r"(a) : "l"(p));
    return a;
}
__device__ __forceinline__ void ldmatrix_x4(uint32_t& a0, uint32_t& a1,
                                            uint32_t& a2, uint32_t& a3,
                                            uint32_t addr) {
    asm volatile("ldmatrix.sync.aligned.m8n8.x4.shared.b16 {%0,%1,%2,%3}, [%4];"
                 : "=r"(a0), "=r"(a1), "=r"(a2), "=r"(a3) : "r"(addr));
}
__device__ __forceinline__ void ldmatrix_x2(uint32_t& b0, uint32_t& b1,
                                            uint32_t addr) {
    asm volatile("ldmatrix.sync.aligned.m8n8.x2.shared.b16 {%0,%1}, [%2];"
                 : "=r"(b0), "=r"(b1) : "r"(addr));
}
__device__ __forceinline__ void mma_bf16(float* c, uint32_t a0, uint32_t a1,
                                         uint32_t a2, uint32_t a3,
                                         uint32_t b0, uint32_t b1) {
    asm volatile(
        "mma.sync.aligned.m16n8k16.row.col.f32.bf16.bf16.f32 "
        "{%0,%1,%2,%3}, {%4,%5,%6,%7}, {%8,%9}, {%0,%1,%2,%3};"
        : "+f"(c[0]), "+f"(c[1]), "+f"(c[2]), "+f"(c[3])
        : "r"(a0), "r"(a1), "r"(a2), "r"(a3), "r"(b0), "r"(b1));
}

// ---------------------------------------------------------------------------
// Dynamic smem layout (bytes)
// ---------------------------------------------------------------------------
#define SM_BQ    0        // 16 hq x 32 j x 16B = 8192
#define SM_AQ    8192     // 8 warps x 16 x 16B = 2048
#define SM_W2H   10240    // 32 rows x 144B = 4608
#define SM_W2L   14848    // 4608
#define SM_STAGE 19456    // 8 warps x 16 rows x 272B = 34816
#define SMEM_TOTAL 54272

// ---------------------------------------------------------------------------
// Main: grid (N/32, N/8), block 256 = 8 warps. Warp w owns i = i0+w, two
// iterations of 16 j's. Phase A: lane computes half a pair's h1 (32 values),
// bf16 hi/lo split, staged as K=128 rows (hi | lo). GEMM on tensor pipe via
// mma.sync bf16: A(hi,lo)·Whi over K=128 + Ahi·Wlo over K=64. C preseeded
// with b2; scalar swish + direct STG.64 epilogue.
// ---------------------------------------------------------------------------
__global__ __launch_bounds__(256, 2) void phi_e_kernel(
    const float* __restrict__ Edges,
    const float* __restrict__ Coords,
    float* __restrict__ out)
{
    extern __shared__ __align__(16) char smem[];
    ulonglong2 (*sBq)[32] = (ulonglong2(*)[32])(smem + SM_BQ);
    ulonglong2 (*sAq)[16] = (ulonglong2(*)[16])(smem + SM_AQ);

    const int tid  = threadIdx.x;
    const int warp = tid >> 5;
    const int lane = tid & 31;
    const int i0 = blockIdx.y * 8;
    const int j0 = blockIdx.x * 32;
    const int i  = i0 + warp;

    // Stage quad-packed B tile for 32 j's.
    {
        const ulonglong2* src = (const ulonglong2*)g_Bq;
        for (int e = tid; e < 16 * 32; e += 256) {
            int hq = e >> 5, jj = e & 31;
            sBq[hq][jj] = src[hq * N_NODES + j0 + jj];
        }
    }
    // Per-warp A quads.
    if (lane < 16)
        ((float4*)&sAq[warp][0])[lane] = ((const float4*)(g_A + i * HID))[lane];
    // Stage W2 hi/lo bf16 tiles: 32 rows x 32 u32 (128 B), rows padded to 144 B.
    // (R16 fix: o = v>>5, c = v&31 — each row is 32 u32, not 16.)
    {
        const uint32_t* hs = (const uint32_t*)g_W2h;
        const uint32_t* ls = (const uint32_t*)g_W2l;
        for (int v = tid; v < OUTF * HID / 2; v += 256) {   // 1024 u32 per tile
            int o = v >> 5, c = v & 31;
            *(uint32_t*)(smem + SM_W2H + o * 144 + c * 4) = hs[v];
            *(uint32_t*)(smem + SM_W2L + o * 144 + c * 4) = ls[v];
        }
    }
    __syncthreads();

    const uint32_t sb = smem_u32(smem);

    // Load W2 fragments (loop-invariant).
    uint32_t bh[4][4][2], bl[4][4][2];
    {
        const int l = lane & 15;
        const uint32_t roff = (uint32_t)((l & 7) * 144 + (l >> 3) * 16);
#pragma unroll
        for (int s = 0; s < 4; s++)
#pragma unroll
            for (int nt = 0; nt < 4; nt++) {
                uint32_t a = sb + SM_W2H + nt * 8 * 144 + roff + s * 32;
                ldmatrix_x2(bh[s][nt][0], bh[s][nt][1], a);
                uint32_t a2 = sb + SM_W2L + nt * 8 * 144 + roff + s * 32;
                ldmatrix_x2(bl[s][nt][0], bl[s][nt][1], a2);
            }
    }

    const int p    = lane & 15;       // pair index within 16-row tile
    const int half = lane >> 4;       // h-half: 0 -> h 0..31, 1 -> h 32..63
    const uint32_t stage_base = sb + SM_STAGE + warp * (16 * 272);
    char* stage_row = smem + SM_STAGE + warp * (16 * 272) + p * 272 + half * 64;

    const float cix = Coords[i * 3 + 0];
    const float ciy = Coords[i * 3 + 1];
    const float ciz = Coords[i * 3 + 2];

#pragma unroll
    for (int wj = 0; wj < 2; wj++) {
        const int j = j0 + wj * 16 + p;
        const int jl = wj * 16 + p;

        // pair weight (both half-lanes compute the same value)
        float e  = Edges[i * N_NODES + j];
        float dx = cix - Coords[j * 3 + 0];
        float dy = ciy - Coords[j * 3 + 1];
        float dz = ciz - Coords[j * 3 + 2];
        float sq = fmaf(dx, dx, fmaf(dy, dy, dz * dz));
        float dist = sq > 0.f ? __fsqrt_rn(sq) : 0.f;
        float w = e * dist;
        const u64 wh = pack2(0.5f * w, 0.5f * w);

        // ---- phase A: 32 h1 values for this lane's half, bf16 hi/lo ----
#pragma unroll
        for (int hq = 0; hq < 8; hq++) {
            const int hqg = half * 8 + hq;
            ulonglong2 aq = sAq[warp][hqg];
            ulonglong2 bq = sBq[hqg][jl];
            u64 b1q0 = *(const u64*)(c_bias + hqg * 4);
            u64 b1q1 = *(const u64*)(c_bias + hqg * 4 + 2);

            u64 x01 = fma2r(wh, add2r(aq.x, bq.x), b1q0);
            u64 x23 = fma2r(wh, add2r(aq.y, bq.y), b1q1);
            float h0, h1, h2, h3;
            unpack2(x01, h0, h1);
            unpack2(x23, h2, h3);
            h0 = swish_from_half(h0); h1 = swish_from_half(h1);
            h2 = swish_from_half(h2); h3 = swish_from_half(h3);

            uint32_t hi0 = cvt_bf16x2(h1, h0);
            uint32_t hi1 = cvt_bf16x2(h3, h2);
            float f0 = __uint_as_float(hi0 << 16);
            float f1 = __uint_as_float(hi0 & 0xffff0000u);
            float f2 = __uint_as_float(hi1 << 16);
            float f3 = __uint_as_float(hi1 & 0xffff0000u);
            uint32_t lo0 = cvt_bf16x2(h1 - f1, h0 - f0);
            uint32_t lo1 = cvt_bf16x2(h3 - f3, h2 - f2);

            *(uint2*)(stage_row + hq * 8)       = make_uint2(hi0, hi1);
            *(uint2*)(stage_row + 128 + hq * 8) = make_uint2(lo0, lo1);
        }
        __syncwarp();

        // ---- GEMM via mma.sync (C preseeded with b2) ----
        const int cb = 2 * (lane & 3);
        float c[4][4];
#pragma unroll
        for (int nt = 0; nt < 4; nt++) {
            c[nt][0] = c_bias[64 + nt * 8 + cb];
            c[nt][1] = c_bias[64 + nt * 8 + cb + 1];
            c[nt][2] = c[nt][0];
            c[nt][3] = c[nt][1];
        }

        const uint32_t arow = stage_base + (uint32_t)((lane & 15) * 272 + (lane >> 4) * 16);
        uint32_t a0, a1, a2, a3;
#pragma unroll
        for (int s = 0; s < 4; s++) {           // k = h 0..63 (hi half of A)
            ldmatrix_x4(a0, a1, a2, a3, arow + s * 32);
#pragma unroll
            for (int nt = 0; nt < 4; nt++) {
                mma_bf16(c[nt], a0, a1, a2, a3, bh[s][nt][0], bh[s][nt][1]);
                mma_bf16(c[nt], a0, a1, a2, a3, bl[s][nt][0], bl[s][nt][1]);
            }
        }
#pragma unroll
        for (int s = 4; s < 8; s++) {           // k = 64..127 (lo half of A) x Whi
            ldmatrix_x4(a0, a1, a2, a3, arow + s * 32);
#pragma unroll
            for (int nt = 0; nt < 4; nt++)
                mma_bf16(c[nt], a0, a1, a2, a3, bh[s - 4][nt][0], bh[s - 4][nt][1]);
        }
        __syncwarp();

        // ---- epilogue: swish + direct STG.64 (rows = pairs, cols = outputs) ----
        const int g = lane >> 2;
        float* ob0 = out + ((size_t)i * N_NODES + j0 + wj * 16 + g) * OUTF + cb;
        float* ob1 = ob0 + (size_t)8 * OUTF;
#pragma unroll
        for (int nt = 0; nt < 4; nt++) {
            float v0 = swish_from_half(0.5f * c[nt][0]);
            float v1 = swish_from_half(0.5f * c[nt][1]);
            float v2 = swish_from_half(0.5f * c[nt][2]);
            float v3 = swish_from_half(0.5f * c[nt][3]);
            __stcs((float2*)(ob0 + nt * 8), make_float2(v0, v1));
            __stcs((float2*)(ob1 + nt * 8), make_float2(v2, v3));
        }
    }
}

// ---------------------------------------------------------------------------
extern "C" void kernel_launch(void* const* d_in, const int* in_sizes, int n_in,
                              void* d_out, int out_size) {
    const float* Edges  = (const float*)d_in[0];
    const float* Coords = (const float*)d_in[1];
    const float* Emb    = (const float*)d_in[2];
    const float* W1     = (const float*)d_in[3];
    const float* b1     = (const float*)d_in[4];
    const float* W2     = (const float*)d_in[5];
    const float* b2     = (const float*)d_in[6];
    float* out = (float*)d_out;

    static bool attr_set = false;
    if (!attr_set) {
        cudaFuncSetAttribute(phi_e_kernel,
                             cudaFuncAttributeMaxDynamicSharedMemorySize,
                             SMEM_TOTAL);
        attr_set = true;
    }

    prep_kernel<<<128, 256>>>(Emb, W1, W2, b1, b2);

    void* bias_dev = nullptr;
    cudaGetSymbolAddress(&bias_dev, g_bias);
    cudaMemcpyToSymbolAsync(c_bias, bias_dev, 96 * sizeof(float), 0,
                            cudaMemcpyDeviceToDevice);

    dim3 grid(N_NODES / 32, N_NODES / 8);
    phi_e_kernel<<<grid, 256, SMEM_TOTAL>>>(Edges, Coords, out);
}